// round 1
// baseline (speedup 1.0000x reference)
#include <cuda_runtime.h>

#define NN 4
#define AA 8732
#define CC 81
#define TPB 256
#define NBLK ((AA + TPB - 1) / TPB)   /* 35 */
#define EPS_IOU 2.220446049250313e-16f

// ---------------- scratch (device globals: allocation-free) ----------------
__device__ float4 g_pbox[NN * AA];
__device__ float4 g_gbox[NN * AA];
__device__ float  g_parea[NN * AA];
__device__ float2 g_gac[NN * AA];     // (g area, con_neg) packed
__device__ float  g_con[NN * AA];
__device__ float  g_conneg[NN * AA];
__device__ float  g_sl1[NN * AA];
__device__ float  g_valid[NN * AA];
__device__ int    g_pos[NN];
__device__ float  g_part1[NN * NBLK];
__device__ float  g_part2[NN * NBLK];

// ---------------- K0: zero pos counters (graph replay safe) ----------------
__global__ void k_zero() {
    if (threadIdx.x < NN) g_pos[threadIdx.x] = 0;
}

// ---------------- K1: per-anchor prep ----------------
__global__ void __launch_bounds__(TPB) k_prep(
    const float* __restrict__ ploc, const float* __restrict__ plabel,
    const float* __restrict__ gloc, const int* __restrict__ glabel,
    const float* __restrict__ dbox)
{
    int n = blockIdx.y;
    int a = blockIdx.x * TPB + threadIdx.x;
    int ismask = 0;
    if (a < AA) {
        float dx = dbox[0 * AA + a], dy = dbox[1 * AA + a];
        float dw = dbox[2 * AA + a], dh = dbox[3 * AA + a];
        const float* pl = ploc + (size_t)n * 4 * AA;
        const float* gg = gloc + (size_t)n * 4 * AA;
        float px = pl[a], py = pl[AA + a], pw = pl[2 * AA + a], ph = pl[3 * AA + a];
        float gx = gg[a], gy = gg[AA + a], gw = gg[2 * AA + a], gh = gg[3 * AA + a];

        // encode targets (vec_gd) + smooth L1
        float gxt = 10.0f * (gx - dx) / dw;
        float gyt = 10.0f * (gy - dy) / dh;
        float gwt = 5.0f * __logf(gw / dw);
        float ght = 5.0f * __logf(gh / dh);

        float s = 0.f, d, ad;
        d = px - gxt; ad = fabsf(d); s += (ad < 1.f) ? 0.5f * d * d : ad - 0.5f;
        d = py - gyt; ad = fabsf(d); s += (ad < 1.f) ? 0.5f * d * d : ad - 0.5f;
        d = pw - gwt; ad = fabsf(d); s += (ad < 1.f) ? 0.5f * d * d : ad - 0.5f;
        d = ph - ght; ad = fabsf(d); s += (ad < 1.f) ? 0.5f * d * d : ad - 0.5f;

        // decode p -> ltrb
        float pcx = 0.1f * px * dw + dx, pcy = 0.1f * py * dh + dy;
        float pww = __expf(0.2f * pw) * dw, phh = __expf(0.2f * ph) * dh;
        float4 pb = make_float4(pcx - 0.5f * pww, pcy - 0.5f * phh,
                                pcx + 0.5f * pww, pcy + 0.5f * phh);
        // decode g -> ltrb (reference runs g through the same decode)
        float gcx = 0.1f * gx * dw + dx, gcy = 0.1f * gy * dh + dy;
        float gww = __expf(0.2f * gw) * dw, ghh = __expf(0.2f * gh) * dh;
        float4 gb = make_float4(gcx - 0.5f * gww, gcy - 0.5f * ghh,
                                gcx + 0.5f * gww, gcy + 0.5f * ghh);

        float pa = (pb.z - pb.x) * (pb.w - pb.y);
        float ga = (gb.z - gb.x) * (gb.w - gb.y);
        int valid = (pb.x < pb.z) && (pb.y < pb.w);

        // con = -log_softmax(plabel)[glabel]
        int lab = glabel[n * AA + a];
        const float* pp = plabel + (size_t)n * CC * AA + a;
        float m = -3.4e38f;
        #pragma unroll 9
        for (int c = 0; c < CC; c++) m = fmaxf(m, pp[(size_t)c * AA]);
        float se = 0.f, xg = 0.f;
        #pragma unroll 9
        for (int c = 0; c < CC; c++) {
            float x = pp[(size_t)c * AA];
            se += __expf(x - m);
            if (c == lab) xg = x;
        }
        float con = __logf(se) + m - xg;
        ismask = (lab > 0);

        int id = n * AA + a;
        float cn = ismask ? 0.f : con;
        g_pbox[id] = pb;
        g_gbox[id] = gb;
        g_parea[id] = pa;
        g_gac[id] = make_float2(ga, cn);
        g_con[id] = con;
        g_conneg[id] = cn;
        g_sl1[id] = s;
        g_valid[id] = valid ? 1.f : 0.f;
    }
    unsigned bal = __ballot_sync(0xffffffffu, ismask);
    if ((threadIdx.x & 31) == 0) atomicAdd(&g_pos[n], __popc(bal));
}

// ---------------- K2: fused A x A IoU-sum + negative ranking + reduce ------
__global__ void __launch_bounds__(TPB) k_main(const int* __restrict__ glabel)
{
    int n = blockIdx.y;
    int i = blockIdx.x * TPB + threadIdx.x;
    int t = threadIdx.x;

    __shared__ float4 sb[TPB];
    __shared__ float2 sgc[TPB];   // (g area, con_neg)
    __shared__ float  r1[TPB];
    __shared__ float  r2[TPB];

    float4 pb = make_float4(0.f, 0.f, 0.f, 0.f);
    float pa = 0.f, ci = 0.f, sl1 = 0.f, con = 0.f, vld = 0.f;
    int lab = 0;
    bool act = (i < AA);
    int id = n * AA + i;
    if (act) {
        pb = g_pbox[id]; pa = g_parea[id]; ci = g_conneg[id];
        sl1 = g_sl1[id]; con = g_con[id]; vld = g_valid[id];
        lab = glabel[id];
    }
    int pos = g_pos[n];
    int K = min(3 * pos, AA);

    float acc[4] = {0.f, 0.f, 0.f, 0.f};
    int cnt = 0;

    for (int jb = 0; jb < AA; jb += TPB) {
        int j = jb + t;
        if (j < AA) {
            int jd = n * AA + j;
            sb[t] = g_gbox[jd];
            sgc[t] = g_gac[jd];
        } else {
            sb[t] = make_float4(1e30f, 1e30f, 1e30f, 1e30f);
            sgc[t] = make_float2(0.f, -1.f);
        }
        __syncthreads();

        #pragma unroll 16
        for (int u = 0; u < TPB; u++) {
            float4 gb = sb[u];
            float2 gc = sgc[u];
            float iw = fmaxf(fminf(pb.z, gb.z) - fmaxf(pb.x, gb.x), 0.f);
            float ih = fmaxf(fminf(pb.w, gb.w) - fmaxf(pb.y, gb.y), 0.f);
            float inter = iw * ih;
            float ua = fmaxf(pa + gc.x - inter, EPS_IOU);
            float r;
            asm("rcp.approx.f32 %0, %1;" : "=f"(r) : "f"(ua));
            acc[u & 3] = fmaf(inter, r, acc[u & 3]);
            cnt += (gc.y > ci);
        }
        __syncthreads();
    }

    float iou_s = (acc[0] + acc[1]) + (acc[2] + acc[3]);
    float w = (vld != 0.f) ? 0.01f * iou_s : 0.f;
    float a1 = 0.f;
    if (act && lab > 0) a1 = sl1 / (sl1 + w) * sl1;
    float a2 = 0.f;
    if (act) {
        float nm = (cnt < K) ? 1.f : 0.f;
        float mm = (lab > 0) ? 1.f : 0.f;
        a2 = con * (mm + nm);
    }

    r1[t] = a1; r2[t] = a2;
    __syncthreads();
    for (int sdim = TPB / 2; sdim > 0; sdim >>= 1) {
        if (t < sdim) { r1[t] += r1[t + sdim]; r2[t] += r2[t + sdim]; }
        __syncthreads();
    }
    if (t == 0) {
        g_part1[n * NBLK + blockIdx.x] = r1[0];
        g_part2[n * NBLK + blockIdx.x] = r2[0];
    }
}

// ---------------- K3: deterministic final reduce ----------------
__global__ void k_final(float* __restrict__ out)
{
    int t = threadIdx.x;
    float val = 0.f;
    if (t < NN) {
        float s1 = 0.f, s2 = 0.f;
        for (int b = 0; b < NBLK; b++) {
            s1 += g_part1[t * NBLK + b];
            s2 += g_part2[t * NBLK + b];
        }
        int pos = g_pos[t];
        if (pos > 0) val = (s1 + s2) / fmaxf((float)pos, 1e-6f);
    }
    #pragma unroll
    for (int o = 16; o > 0; o >>= 1) val += __shfl_down_sync(0xffffffffu, val, o);
    if (t == 0) out[0] = val * (1.0f / NN);
}

// ---------------- launch ----------------
extern "C" void kernel_launch(void* const* d_in, const int* in_sizes, int n_in,
                              void* d_out, int out_size)
{
    const float* ploc   = (const float*)d_in[0];
    const float* plabel = (const float*)d_in[1];
    const float* gloc   = (const float*)d_in[2];
    const int*   glabel = (const int*)d_in[3];
    const float* dbox   = (const float*)d_in[4];
    float* out = (float*)d_out;

    dim3 grid(NBLK, NN);
    k_zero<<<1, 32>>>();
    k_prep<<<grid, TPB>>>(ploc, plabel, gloc, glabel, dbox);
    k_main<<<grid, TPB>>>(glabel);
    k_final<<<1, 32>>>(out);
}

// round 2
// speedup vs baseline: 1.4317x; 1.4317x over previous
#include <cuda_runtime.h>

#define NN 4
#define AA 8732
#define CC 81
#define TPB 256
#define NBLK ((AA + TPB - 1) / TPB)     /* 35 */
#define IT 4
#define ITILE (TPB * IT)                /* 1024 */
#define NBI ((AA + ITILE - 1) / ITILE)  /* 9 */
#define SPLIT 12
#define JCH 768                         /* 12*768 = 9216 >= 8732 */
#define EPS_IOU 2.220446049250313e-16f

// ---------------- scratch (device globals: allocation-free) ----------------
__device__ float4 g_pbox[NN * AA];
__device__ float4 g_gbox[NN * AA];
__device__ float  g_parea[NN * AA];
__device__ float2 g_gac[NN * AA];     // (g area, con_neg) packed
__device__ float  g_con[NN * AA];
__device__ float  g_conneg[NN * AA];
__device__ float  g_sl1[NN * AA];
__device__ float  g_valid[NN * AA];
__device__ int    g_pos[NN];
__device__ float  g_ioup[SPLIT][NN * AA];
__device__ int    g_cntp[SPLIT][NN * AA];
__device__ float  g_part1[NN * NBLK];
__device__ float  g_part2[NN * NBLK];

// ---------------- K0: zero pos counters (graph replay safe) ----------------
__global__ void k_zero() {
    if (threadIdx.x < NN) g_pos[threadIdx.x] = 0;
}

// ---------------- K1: per-anchor prep ----------------
__global__ void __launch_bounds__(TPB) k_prep(
    const float* __restrict__ ploc, const float* __restrict__ plabel,
    const float* __restrict__ gloc, const int* __restrict__ glabel,
    const float* __restrict__ dbox)
{
    int n = blockIdx.y;
    int a = blockIdx.x * TPB + threadIdx.x;
    int ismask = 0;
    if (a < AA) {
        float dx = dbox[0 * AA + a], dy = dbox[1 * AA + a];
        float dw = dbox[2 * AA + a], dh = dbox[3 * AA + a];
        const float* pl = ploc + (size_t)n * 4 * AA;
        const float* gg = gloc + (size_t)n * 4 * AA;
        float px = pl[a], py = pl[AA + a], pw = pl[2 * AA + a], ph = pl[3 * AA + a];
        float gx = gg[a], gy = gg[AA + a], gw = gg[2 * AA + a], gh = gg[3 * AA + a];

        // encode targets (vec_gd) + smooth L1
        float gxt = 10.0f * (gx - dx) / dw;
        float gyt = 10.0f * (gy - dy) / dh;
        float gwt = 5.0f * __logf(gw / dw);
        float ght = 5.0f * __logf(gh / dh);

        float s = 0.f, d, ad;
        d = px - gxt; ad = fabsf(d); s += (ad < 1.f) ? 0.5f * d * d : ad - 0.5f;
        d = py - gyt; ad = fabsf(d); s += (ad < 1.f) ? 0.5f * d * d : ad - 0.5f;
        d = pw - gwt; ad = fabsf(d); s += (ad < 1.f) ? 0.5f * d * d : ad - 0.5f;
        d = ph - ght; ad = fabsf(d); s += (ad < 1.f) ? 0.5f * d * d : ad - 0.5f;

        // decode p -> ltrb
        float pcx = 0.1f * px * dw + dx, pcy = 0.1f * py * dh + dy;
        float pww = __expf(0.2f * pw) * dw, phh = __expf(0.2f * ph) * dh;
        float4 pb = make_float4(pcx - 0.5f * pww, pcy - 0.5f * phh,
                                pcx + 0.5f * pww, pcy + 0.5f * phh);
        // decode g -> ltrb (reference runs g through the same decode)
        float gcx = 0.1f * gx * dw + dx, gcy = 0.1f * gy * dh + dy;
        float gww = __expf(0.2f * gw) * dw, ghh = __expf(0.2f * gh) * dh;
        float4 gb = make_float4(gcx - 0.5f * gww, gcy - 0.5f * ghh,
                                gcx + 0.5f * gww, gcy + 0.5f * ghh);

        float pa = (pb.z - pb.x) * (pb.w - pb.y);
        float ga = (gb.z - gb.x) * (gb.w - gb.y);
        int valid = (pb.x < pb.z) && (pb.y < pb.w);

        // con = -log_softmax(plabel)[glabel]
        int lab = glabel[n * AA + a];
        const float* pp = plabel + (size_t)n * CC * AA + a;
        float m = -3.4e38f;
        #pragma unroll 9
        for (int c = 0; c < CC; c++) m = fmaxf(m, pp[(size_t)c * AA]);
        float se = 0.f, xg = 0.f;
        #pragma unroll 9
        for (int c = 0; c < CC; c++) {
            float x = pp[(size_t)c * AA];
            se += __expf(x - m);
            if (c == lab) xg = x;
        }
        float con = __logf(se) + m - xg;
        ismask = (lab > 0);

        int id = n * AA + a;
        float cn = ismask ? 0.f : con;
        g_pbox[id] = pb;
        g_gbox[id] = gb;
        g_parea[id] = pa;
        g_gac[id] = make_float2(ga, cn);
        g_con[id] = con;
        g_conneg[id] = cn;
        g_sl1[id] = s;
        g_valid[id] = valid ? 1.f : 0.f;
    }
    unsigned bal = __ballot_sync(0xffffffffu, ismask);
    if ((threadIdx.x & 31) == 0) atomicAdd(&g_pos[n], __popc(bal));
}

// ------- K2: A x A IoU-sum + negative ranking, j-split for occupancy -------
__global__ void __launch_bounds__(TPB) k_main()
{
    int n = blockIdx.z;
    int s = blockIdx.y;
    int t = threadIdx.x;
    int ibase = blockIdx.x * ITILE + t;

    __shared__ float4 sb[TPB];
    __shared__ float2 sgc[TPB];

    float4 pb[IT];
    float  pa[IT], ci[IT], acc[IT];
    int    cnt[IT];
    bool   act[IT];

    #pragma unroll
    for (int k = 0; k < IT; k++) {
        int i = ibase + k * TPB;
        act[k] = (i < AA);
        if (act[k]) {
            int id = n * AA + i;
            pb[k] = g_pbox[id]; pa[k] = g_parea[id]; ci[k] = g_conneg[id];
        } else {
            pb[k] = make_float4(-2e30f, -2e30f, -2e30f, -2e30f);
            pa[k] = 0.f; ci[k] = 3.0e38f;
        }
        acc[k] = 0.f; cnt[k] = 0;
    }

    int j0 = s * JCH;
    int j1 = min(AA, j0 + JCH);

    for (int jb = j0; jb < j1; jb += TPB) {
        int j = jb + t;
        if (j < j1) {
            int jd = n * AA + j;
            sb[t] = g_gbox[jd];
            sgc[t] = g_gac[jd];
        } else {
            sb[t] = make_float4(1e30f, 1e30f, 1e30f, 1e30f);
            sgc[t] = make_float2(0.f, -1e30f);
        }
        __syncthreads();

        #pragma unroll 4
        for (int u = 0; u < TPB; u++) {
            float4 gb = sb[u];
            float2 gc = sgc[u];
            #pragma unroll
            for (int k = 0; k < IT; k++) {
                float iw = fmaxf(fminf(pb[k].z, gb.z) - fmaxf(pb[k].x, gb.x), 0.f);
                float ih = fmaxf(fminf(pb[k].w, gb.w) - fmaxf(pb[k].y, gb.y), 0.f);
                float inter = iw * ih;
                float ua = fmaxf(pa[k] + gc.x - inter, EPS_IOU);
                float r;
                asm("rcp.approx.f32 %0, %1;" : "=f"(r) : "f"(ua));
                acc[k] = fmaf(inter, r, acc[k]);
                cnt[k] += (gc.y > ci[k]);
            }
        }
        __syncthreads();
    }

    #pragma unroll
    for (int k = 0; k < IT; k++) {
        if (act[k]) {
            int id = n * AA + ibase + k * TPB;
            g_ioup[s][id] = acc[k];
            g_cntp[s][id] = cnt[k];
        }
    }
}

// ------- K3: combine partials (fixed order), epilogue + block reduce -------
__global__ void __launch_bounds__(TPB) k_post(const int* __restrict__ glabel)
{
    int n = blockIdx.y;
    int i = blockIdx.x * TPB + threadIdx.x;
    int t = threadIdx.x;

    float a1 = 0.f, a2 = 0.f;
    if (i < AA) {
        int id = n * AA + i;
        float iou = 0.f;
        int cnt = 0;
        #pragma unroll
        for (int s = 0; s < SPLIT; s++) {
            iou += g_ioup[s][id];
            cnt += g_cntp[s][id];
        }
        int pos = g_pos[n];
        int K = min(3 * pos, AA);
        float sl1 = g_sl1[id], con = g_con[id], vld = g_valid[id];
        int lab = glabel[id];

        float w = (vld != 0.f) ? 0.01f * iou : 0.f;
        if (lab > 0) a1 = sl1 / (sl1 + w) * sl1;
        float nm = (cnt < K) ? 1.f : 0.f;
        float mm = (lab > 0) ? 1.f : 0.f;
        a2 = con * (mm + nm);
    }

    __shared__ float r1[TPB];
    __shared__ float r2[TPB];
    r1[t] = a1; r2[t] = a2;
    __syncthreads();
    for (int sdim = TPB / 2; sdim > 0; sdim >>= 1) {
        if (t < sdim) { r1[t] += r1[t + sdim]; r2[t] += r2[t + sdim]; }
        __syncthreads();
    }
    if (t == 0) {
        g_part1[n * NBLK + blockIdx.x] = r1[0];
        g_part2[n * NBLK + blockIdx.x] = r2[0];
    }
}

// ---------------- K4: deterministic final reduce ----------------
__global__ void k_final(float* __restrict__ out)
{
    int t = threadIdx.x;
    float val = 0.f;
    if (t < NN) {
        float s1 = 0.f, s2 = 0.f;
        for (int b = 0; b < NBLK; b++) {
            s1 += g_part1[t * NBLK + b];
            s2 += g_part2[t * NBLK + b];
        }
        int pos = g_pos[t];
        if (pos > 0) val = (s1 + s2) / fmaxf((float)pos, 1e-6f);
    }
    #pragma unroll
    for (int o = 16; o > 0; o >>= 1) val += __shfl_down_sync(0xffffffffu, val, o);
    if (t == 0) out[0] = val * (1.0f / NN);
}

// ---------------- launch ----------------
extern "C" void kernel_launch(void* const* d_in, const int* in_sizes, int n_in,
                              void* d_out, int out_size)
{
    const float* ploc   = (const float*)d_in[0];
    const float* plabel = (const float*)d_in[1];
    const float* gloc   = (const float*)d_in[2];
    const int*   glabel = (const int*)d_in[3];
    const float* dbox   = (const float*)d_in[4];
    float* out = (float*)d_out;

    k_zero<<<1, 32>>>();
    k_prep<<<dim3(NBLK, NN), TPB>>>(ploc, plabel, gloc, glabel, dbox);
    k_main<<<dim3(NBI, SPLIT, NN), TPB>>>();
    k_post<<<dim3(NBLK, NN), TPB>>>(glabel);
    k_final<<<1, 32>>>(out);
}